// round 1
// baseline (speedup 1.0000x reference)
#include <cuda_runtime.h>
#include <math.h>

#define TQ 64
#define IQ 9
#define NQ 128
#define VQ 20
#define CQ 100
#define OQ 8
#define GQ 4
#define BLK 128
#define EPSQ 1e-8f
#define MPAD 21

// p_s column map (92 transformed head params, layout [col][G]):
//  read head : k 0..19 | beta 20 | g 21 | s 22..24 | gamma 25
//  write head: k 26..45 | beta 46 | g 47 | s 48..50 | gamma 51 | e 52..71 | a 72..91

__device__ __forceinline__ float softplusf_(float x) {
    return fmaxf(x, 0.f) + log1pf(expf(-fabsf(x)));
}
__device__ __forceinline__ float sigmoidf_(float x) {
    return 1.f / (1.f + expf(-x));
}
__device__ __forceinline__ float warp_sum(float v) {
    v += __shfl_xor_sync(0xffffffffu, v, 16);
    v += __shfl_xor_sync(0xffffffffu, v, 8);
    v += __shfl_xor_sync(0xffffffffu, v, 4);
    v += __shfl_xor_sync(0xffffffffu, v, 2);
    v += __shfl_xor_sync(0xffffffffu, v, 1);
    return v;
}

__global__ __launch_bounds__(BLK) void ntm_kernel(
    const float* __restrict__ x,
    const float* __restrict__ Wc, const float* __restrict__ bc,
    const float* __restrict__ Wr, const float* __restrict__ br,
    const float* __restrict__ Ww, const float* __restrict__ bw,
    const float* __restrict__ Wf, const float* __restrict__ bf,
    const float* __restrict__ r_bias, const float* __restrict__ M_bias,
    float* __restrict__ out)
{
    extern __shared__ float sm[];
    float* M_s  = sm;                       // [G][128][MPAD]   10752 floats
    float* wbuf = M_s + GQ * NQ * MPAD;     // [G][128]         conv staging
    float* wr_s = wbuf + GQ * NQ;           // [G][128]         normalized read weights
    float* z_s  = wr_s + GQ * NQ;           // [32][G]          controller input (x|r), transposed
    float* h_s  = z_s + 32 * GQ;            // [100][G]         controller hidden, transposed
    float* p_s  = h_s + CQ * GQ;            // [92][G]          head params, transposed
    float* kn_s = p_s + 92 * GQ;            // [2][G]           key norms
    float* red  = kn_s + 2 * GQ;            // [2][G][4]        block-reduce partials

    const int tid  = threadIdx.x;
    const int lane = tid & 31;
    const int warp = tid >> 5;
    const int n    = tid;                   // memory row this thread owns
    const int b0   = blockIdx.x * GQ;

    // ---- init state ----
    float w_prev[GQ];
    #pragma unroll
    for (int g = 0; g < GQ; g++) w_prev[g] = 0.f;
    #pragma unroll
    for (int g = 0; g < GQ; g++) {
        #pragma unroll
        for (int v = 0; v < VQ; v++)
            M_s[(g * NQ + n) * MPAD + v] = M_bias[n * VQ + v];
    }
    if (tid < VQ * GQ) {                    // r0 = r_bias
        int g = tid & 3, v = tid >> 2;
        z_s[(IQ + v) * GQ + g] = r_bias[v];
    }
    __syncthreads();

    for (int t = 0; t < TQ; t++) {
        // ---- P0: load x_t into z_s[0..8][g] ----
        if (tid < IQ * GQ) {
            int g = tid / IQ, i = tid - g * IQ;
            z_s[i * GQ + g] = x[((b0 + g) * TQ + t) * IQ + i];
        }
        __syncthreads();

        // ---- P1: controller h = tanh([x,r] @ Wc + bc) ----
        if (tid < CQ) {
            float a0 = bc[tid], a1 = a0, a2 = a0, a3 = a0;
            #pragma unroll
            for (int j = 0; j < IQ + VQ; j++) {
                float w = Wc[j * CQ + tid];
                float4 zv = *(const float4*)&z_s[j * GQ];
                a0 = fmaf(w, zv.x, a0); a1 = fmaf(w, zv.y, a1);
                a2 = fmaf(w, zv.z, a2); a3 = fmaf(w, zv.w, a3);
            }
            h_s[tid * GQ + 0] = tanhf(a0); h_s[tid * GQ + 1] = tanhf(a1);
            h_s[tid * GQ + 2] = tanhf(a2); h_s[tid * GQ + 3] = tanhf(a3);
        }
        __syncthreads();

        // ---- P2: both head matvecs (26 + 66 output cols) ----
        if (tid < 92) {
            const float* Wp; int od, cc; float bsv;
            if (tid < 26) { Wp = Wr; od = 26; cc = tid;      bsv = br[cc]; }
            else          { Wp = Ww; od = 66; cc = tid - 26; bsv = bw[cc]; }
            float a0 = bsv, a1 = bsv, a2 = bsv, a3 = bsv;
            #pragma unroll 4
            for (int j = 0; j < CQ; j++) {
                float w = Wp[j * od + cc];
                float4 hv = *(const float4*)&h_s[j * GQ];
                a0 = fmaf(w, hv.x, a0); a1 = fmaf(w, hv.y, a1);
                a2 = fmaf(w, hv.z, a2); a3 = fmaf(w, hv.w, a3);
            }
            p_s[tid * GQ + 0] = a0; p_s[tid * GQ + 1] = a1;
            p_s[tid * GQ + 2] = a2; p_s[tid * GQ + 3] = a3;
        }
        __syncthreads();

        // ---- P3: per-scalar activations (in place) ----
        for (int idx = tid; idx < 92 * GQ; idx += BLK) {
            int col = idx >> 2;
            float v = p_s[idx], r;
            if      (col < 20)  r = tanhf(v);
            else if (col == 20) r = softplusf_(v);
            else if (col == 21) r = sigmoidf_(v);
            else if (col < 25)  r = expf(v);            // s (normalized in P4)
            else if (col == 25) r = 1.f + softplusf_(v);
            else if (col < 46)  r = tanhf(v);
            else if (col == 46) r = softplusf_(v);
            else if (col == 47) r = sigmoidf_(v);
            else if (col < 51)  r = expf(v);
            else if (col == 51) r = 1.f + softplusf_(v);
            else if (col < 72)  r = sigmoidf_(v);       // e
            else                r = tanhf(v);           // a
            p_s[idx] = r;
        }
        __syncthreads();

        // ---- P4: key norms + shift-softmax normalize ----
        if (tid < 8) {
            int hh = tid >> 2, g = tid & 3;
            int base = hh ? 26 : 0;
            float s2 = 0.f;
            #pragma unroll
            for (int v = 0; v < VQ; v++) { float kv = p_s[(base + v) * GQ + g]; s2 = fmaf(kv, kv, s2); }
            kn_s[hh * GQ + g] = sqrtf(s2);
        } else if (tid < 16) {
            int tt = tid - 8; int hh = tt >> 2, g = tt & 3;
            int sb = hh ? 48 : 22;
            float e0 = p_s[sb * GQ + g], e1 = p_s[(sb + 1) * GQ + g], e2 = p_s[(sb + 2) * GQ + g];
            float inv = 1.f / (e0 + e1 + e2);
            p_s[sb * GQ + g] = e0 * inv; p_s[(sb + 1) * GQ + g] = e1 * inv; p_s[(sb + 2) * GQ + g] = e2 * inv;
        }
        __syncthreads();

        // ---- P5: fused content addressing for BOTH heads (one M pass) ----
        float er[GQ], ew[GQ];
        #pragma unroll
        for (int g = 0; g < GQ; g++) {
            float knr = kn_s[g], knw = kn_s[GQ + g];
            float betar = p_s[20 * GQ + g], betaw = p_s[46 * GQ + g];
            float dr = 0.f, dw = 0.f, n2 = 0.f;
            const float* Mrow = &M_s[(g * NQ + n) * MPAD];
            #pragma unroll
            for (int v = 0; v < VQ; v++) {
                float m = Mrow[v];
                dr = fmaf(p_s[v * GQ + g], m, dr);
                dw = fmaf(p_s[(26 + v) * GQ + g], m, dw);
                n2 = fmaf(m, m, n2);
            }
            float mn = sqrtf(n2);
            er[g] = expf(betar * (dr / (knr * mn + EPSQ)));
            ew[g] = expf(betaw * (dw / (knw * mn + EPSQ)));
            float sr = warp_sum(er[g]);
            float sw = warp_sum(ew[g]);
            if (lane == 0) { red[g * 4 + warp] = sr; red[16 + g * 4 + warp] = sw; }
        }
        __syncthreads();

        // ---- P6: softmax sums; read-head interpolation -> wbuf ----
        float sumw[GQ];
        #pragma unroll
        for (int g = 0; g < GQ; g++) {
            float se = red[g * 4 + 0] + red[g * 4 + 1] + red[g * 4 + 2] + red[g * 4 + 3];
            sumw[g]  = red[16 + g * 4 + 0] + red[16 + g * 4 + 1] + red[16 + g * 4 + 2] + red[16 + g * 4 + 3];
            float gr = p_s[21 * GQ + g];
            wbuf[g * NQ + n] = gr * (er[g] / se) + (1.f - gr) * w_prev[g];
        }
        __syncthreads();

        // ---- P7: read-head circular conv + sharpen ----
        float wpr[GQ];
        #pragma unroll
        for (int g = 0; g < GQ; g++) {
            float s0 = p_s[22 * GQ + g], s1 = p_s[23 * GQ + g], s2 = p_s[24 * GQ + g];
            float gam = p_s[25 * GQ + g];
            const float* wb = &wbuf[g * NQ];
            float ws = s0 * wb[(n + 1) & 127] + s1 * wb[n] + s2 * wb[(n - 1) & 127];
            wpr[g] = expf(gam * logf(ws));
            float sp = warp_sum(wpr[g]);
            if (lane == 0) red[g * 4 + warp] = sp;
        }
        __syncthreads();

        // ---- P8: normalize w_r; write-head interpolation (w_prev = w_r) -> wbuf ----
        #pragma unroll
        for (int g = 0; g < GQ; g++) {
            float sp = red[g * 4 + 0] + red[g * 4 + 1] + red[g * 4 + 2] + red[g * 4 + 3];
            float wr = wpr[g] / (sp + EPSQ);
            wr_s[g * NQ + n] = wr;
            float gw = p_s[47 * GQ + g];
            wbuf[g * NQ + n] = gw * (ew[g] / sumw[g]) + (1.f - gw) * wr;
        }
        __syncthreads();

        // ---- P9a: r = w_r @ M  (warp-per-batch) ----
        {
            int g = warp;
            const float* wrp = &wr_s[g * NQ];
            float w0 = wrp[lane], w1 = wrp[lane + 32], w2 = wrp[lane + 64], w3 = wrp[lane + 96];
            const float* Mg = &M_s[g * NQ * MPAD];
            #pragma unroll
            for (int v = 0; v < VQ; v++) {
                float acc = w0 * Mg[lane * MPAD + v] + w1 * Mg[(lane + 32) * MPAD + v]
                          + w2 * Mg[(lane + 64) * MPAD + v] + w3 * Mg[(lane + 96) * MPAD + v];
                acc = warp_sum(acc);
                if (lane == 0) z_s[(IQ + v) * GQ + g] = acc;
            }
        }
        // ---- P9b: write-head conv + sharpen (independent of P9a) ----
        float wpw[GQ];
        #pragma unroll
        for (int g = 0; g < GQ; g++) {
            float s0 = p_s[48 * GQ + g], s1 = p_s[49 * GQ + g], s2 = p_s[50 * GQ + g];
            float gam = p_s[51 * GQ + g];
            const float* wb = &wbuf[g * NQ];
            float ws = s0 * wb[(n + 1) & 127] + s1 * wb[n] + s2 * wb[(n - 1) & 127];
            wpw[g] = expf(gam * logf(ws));
            float sp = warp_sum(wpw[g]);
            if (lane == 0) red[g * 4 + warp] = sp;
        }
        __syncthreads();

        // ---- P10: normalize w_w; M update; output ----
        #pragma unroll
        for (int g = 0; g < GQ; g++) {
            float sp = red[g * 4 + 0] + red[g * 4 + 1] + red[g * 4 + 2] + red[g * 4 + 3];
            float ww = wpw[g] / (sp + EPSQ);
            w_prev[g] = ww;                     // carry: next step's read-head w_prev
            float* Mrow = &M_s[(g * NQ + n) * MPAD];
            #pragma unroll
            for (int v = 0; v < VQ; v++) {
                float e = p_s[(52 + v) * GQ + g];
                float a = p_s[(72 + v) * GQ + g];
                float m = Mrow[v];
                float we = ww * e;
                m = fmaf(-we, m, m);            // m*(1 - w*e)
                m = fmaf(ww, a, m);             // + w*a
                Mrow[v] = m;
            }
        }
        // out = sigmoid([h, r] @ Wf + bf)   (warp-per-batch, 8 outs x 4 partials)
        {
            int g = warp;
            int o = lane & 7, part = lane >> 3;
            float acc = 0.f;
            int j0 = part * 30;
            #pragma unroll 5
            for (int j = j0; j < j0 + 30; j++) {
                float c = (j < CQ) ? h_s[j * GQ + g] : z_s[(IQ + (j - CQ)) * GQ + g];
                acc = fmaf(c, Wf[j * OQ + o], acc);
            }
            acc += __shfl_xor_sync(0xffffffffu, acc, 8);
            acc += __shfl_xor_sync(0xffffffffu, acc, 16);
            if (lane < 8)
                out[((b0 + g) * TQ + t) * OQ + o] = sigmoidf_(acc + bf[o]);
        }
        __syncthreads();
    }
}

extern "C" void kernel_launch(void* const* d_in, const int* in_sizes, int n_in,
                              void* d_out, int out_size) {
    const float* x      = (const float*)d_in[0];
    const float* Wc     = (const float*)d_in[1];
    const float* bc     = (const float*)d_in[2];
    const float* Wr     = (const float*)d_in[3];
    const float* br     = (const float*)d_in[4];
    const float* Ww     = (const float*)d_in[5];
    const float* bw     = (const float*)d_in[6];
    const float* Wf     = (const float*)d_in[7];
    const float* bf     = (const float*)d_in[8];
    const float* r_bias = (const float*)d_in[9];
    const float* M_bias = (const float*)d_in[10];

    int B = in_sizes[0] / (TQ * IQ);        // 2048
    int grid = B / GQ;                      // 512

    size_t smem = (size_t)(GQ * NQ * MPAD + 2 * GQ * NQ + 32 * GQ + CQ * GQ
                           + 92 * GQ + 2 * GQ + 32) * sizeof(float);  // 50848 B
    cudaFuncSetAttribute(ntm_kernel, cudaFuncAttributeMaxDynamicSharedMemorySize, (int)smem);

    ntm_kernel<<<grid, BLK, smem>>>(x, Wc, bc, Wr, br, Ww, bw, Wf, bf,
                                    r_bias, M_bias, (float*)d_out);
}

// round 3
// speedup vs baseline: 1.2813x; 1.2813x over previous
#include <cuda_runtime.h>
#include <math.h>

#define TQ 64
#define IQ 9
#define NQ 128
#define VQ 20
#define CQ 100
#define OQ 8
#define GQ 4
#define BLK 128
#define EPSQ 1e-8f
#define MPAD 21

// p_s column map (92 head params, layout [col][G]):
//  read head : k 0..19 | beta 20 | g 21 | s 22..24 | gamma 25
//  write head: k 26..45 | beta 46 | g 47 | s 48..50 | gamma 51 | e 52..71 | a 72..91

__device__ __forceinline__ float fdiv_(float a, float b) { return __fdividef(a, b); }
__device__ __forceinline__ float ftanh_(float x) {
    float xc = fminf(fmaxf(x, -15.f), 15.f);
    float e = __expf(2.f * xc);
    return __fdividef(e - 1.f, e + 1.f);
}
__device__ __forceinline__ float fsoftplus_(float x) {
    return fmaxf(x, 0.f) + __logf(1.f + __expf(-fabsf(x)));
}
__device__ __forceinline__ float fsigmoid_(float x) {
    return __fdividef(1.f, 1.f + __expf(-x));
}
__device__ __forceinline__ float warp_sum(float v) {
    v += __shfl_xor_sync(0xffffffffu, v, 16);
    v += __shfl_xor_sync(0xffffffffu, v, 8);
    v += __shfl_xor_sync(0xffffffffu, v, 4);
    v += __shfl_xor_sync(0xffffffffu, v, 2);
    v += __shfl_xor_sync(0xffffffffu, v, 1);
    return v;
}

__global__ __launch_bounds__(BLK, 4) void ntm_kernel(
    const float* __restrict__ x,
    const float* __restrict__ Wc, const float* __restrict__ bc,
    const float* __restrict__ Wr, const float* __restrict__ br,
    const float* __restrict__ Ww, const float* __restrict__ bw,
    const float* __restrict__ Wf, const float* __restrict__ bf,
    const float* __restrict__ r_bias, const float* __restrict__ M_bias,
    float* __restrict__ out)
{
    extern __shared__ float sm[];
    float* M_s     = sm;                        // [G][128][21]  10752
    float* wbuf    = M_s + GQ * NQ * MPAD;      // [G][128]      conv staging
    float* wr_s    = wbuf + GQ * NQ;            // [G][128]      er-unnorm -> wp-unnorm -> w_r
    float* ew_s    = wr_s + GQ * NQ;            // [G][128]      ew-unnorm -> wpw-unnorm
    float* wprev_s = ew_s + GQ * NQ;            // [G][128]      read-head prev weights
    float* z_s     = wprev_s + GQ * NQ;         // [32][G]       controller input (x|r)
    float* h_s     = z_s + 32 * GQ;             // [100][G]      controller hidden
    float* p_s     = h_s + CQ * GQ;             // [92][G]       head params
    float* red     = p_s + 92 * GQ;             // [2][G][4]     block-reduce partials

    const int tid  = threadIdx.x;
    const int lane = tid & 31;
    const int warp = tid >> 5;
    const int n    = tid;                       // memory row this thread owns
    const int b0   = blockIdx.x * GQ;

    // hoisted per-thread constants
    float bcv = (tid < CQ) ? bc[tid] : 0.f;
    const float* Wp; int od = 0, cc = 0; float bsv = 0.f;
    if (tid < 26)      { Wp = Wr; od = 26; cc = tid;      bsv = br[cc]; }
    else if (tid < 92) { Wp = Ww; od = 66; cc = tid - 26; bsv = bw[cc]; }
    else               { Wp = Ww; }
    float bfv = bf[lane & 7];

    // ---- init state ----
    #pragma unroll
    for (int g = 0; g < GQ; g++) {
        wprev_s[g * NQ + n] = 0.f;
        #pragma unroll
        for (int v = 0; v < VQ; v++)
            M_s[(g * NQ + n) * MPAD + v] = M_bias[n * VQ + v];
    }
    if (tid < VQ * GQ) {                        // r0 = r_bias
        int g = tid & 3, v = tid >> 2;
        z_s[(IQ + v) * GQ + g] = r_bias[v];
    }
    if (tid < IQ * GQ) {                        // x_0
        int g = tid / IQ, i = tid - g * IQ;
        z_s[i * GQ + g] = x[(b0 + g) * TQ * IQ + i];
    }
    __syncthreads();

    for (int t = 0; t < TQ; t++) {
        // ---- P1: controller h = tanh([x,r] @ Wc + bc) ----
        if (tid < CQ) {
            float a0 = bcv, a1 = bcv, a2 = bcv, a3 = bcv;
            #pragma unroll
            for (int j = 0; j < IQ + VQ; j++) {
                float w = Wc[j * CQ + tid];
                float4 zv = *(const float4*)&z_s[j * GQ];
                a0 = fmaf(w, zv.x, a0); a1 = fmaf(w, zv.y, a1);
                a2 = fmaf(w, zv.z, a2); a3 = fmaf(w, zv.w, a3);
            }
            h_s[tid * GQ + 0] = ftanh_(a0); h_s[tid * GQ + 1] = ftanh_(a1);
            h_s[tid * GQ + 2] = ftanh_(a2); h_s[tid * GQ + 3] = ftanh_(a3);
        }
        __syncthreads();

        // ---- P2: both head matvecs (26 + 66 output cols) ----
        if (tid < 92) {
            float a0 = bsv, a1 = bsv, a2 = bsv, a3 = bsv;
            #pragma unroll 4
            for (int j = 0; j < CQ; j++) {
                float w = Wp[j * od + cc];
                float4 hv = *(const float4*)&h_s[j * GQ];
                a0 = fmaf(w, hv.x, a0); a1 = fmaf(w, hv.y, a1);
                a2 = fmaf(w, hv.z, a2); a3 = fmaf(w, hv.w, a3);
            }
            p_s[tid * GQ + 0] = a0; p_s[tid * GQ + 1] = a1;
            p_s[tid * GQ + 2] = a2; p_s[tid * GQ + 3] = a3;
        }
        __syncthreads();

        // ---- P3: per-scalar activations (in place) ----
        for (int idx = tid; idx < 92 * GQ; idx += BLK) {
            int col = idx >> 2;
            float v = p_s[idx], r;
            if      (col < 20)  r = ftanh_(v);
            else if (col == 20) r = fsoftplus_(v);
            else if (col == 21) r = fsigmoid_(v);
            else if (col < 25)  r = __expf(v);           // s (normalized in P5 tail)
            else if (col == 25) r = 1.f + fsoftplus_(v);
            else if (col < 46)  r = ftanh_(v);
            else if (col == 46) r = fsoftplus_(v);
            else if (col == 47) r = fsigmoid_(v);
            else if (col < 51)  r = __expf(v);
            else if (col == 51) r = 1.f + fsoftplus_(v);
            else if (col < 72)  r = fsigmoid_(v);        // e
            else                r = ftanh_(v);           // a
            p_s[idx] = r;
        }
        __syncthreads();

        // ---- P5: fused content addressing for BOTH heads (norms inline) ----
        #pragma unroll
        for (int g = 0; g < GQ; g++) {
            float betar = p_s[20 * GQ + g], betaw = p_s[46 * GQ + g];
            float dr = 0.f, dw = 0.f, n2 = 0.f, kr2 = 0.f, kw2 = 0.f;
            const float* Mrow = &M_s[(g * NQ + n) * MPAD];
            #pragma unroll
            for (int v = 0; v < VQ; v++) {
                float m  = Mrow[v];
                float kr = p_s[v * GQ + g];
                float kw = p_s[(26 + v) * GQ + g];
                dr = fmaf(kr, m, dr); dw = fmaf(kw, m, dw);
                n2 = fmaf(m, m, n2);
                kr2 = fmaf(kr, kr, kr2); kw2 = fmaf(kw, kw, kw2);
            }
            float mn = sqrtf(n2);
            float er = __expf(betar * fdiv_(dr, sqrtf(kr2) * mn + EPSQ));
            float ew = __expf(betaw * fdiv_(dw, sqrtf(kw2) * mn + EPSQ));
            wr_s[g * NQ + n] = er;
            ew_s[g * NQ + n] = ew;
            float sr = warp_sum(er);
            float sw = warp_sum(ew);
            if (lane == 0) { red[g * 4 + warp] = sr; red[16 + g * 4 + warp] = sw; }
        }
        // shift-softmax normalize (2 heads x 4 batch)
        if (tid < 8) {
            int hh = tid >> 2, g = tid & 3;
            int sb = hh ? 48 : 22;
            float e0 = p_s[sb * GQ + g], e1 = p_s[(sb + 1) * GQ + g], e2 = p_s[(sb + 2) * GQ + g];
            float inv = fdiv_(1.f, e0 + e1 + e2);
            p_s[sb * GQ + g] = e0 * inv; p_s[(sb + 1) * GQ + g] = e1 * inv; p_s[(sb + 2) * GQ + g] = e2 * inv;
        }
        __syncthreads();

        // ---- P6: read-head softmax + interpolation -> wbuf ----
        #pragma unroll
        for (int g = 0; g < GQ; g++) {
            float se = red[g * 4 + 0] + red[g * 4 + 1] + red[g * 4 + 2] + red[g * 4 + 3];
            float gr = p_s[21 * GQ + g];
            wbuf[g * NQ + n] = gr * fdiv_(wr_s[g * NQ + n], se)
                             + (1.f - gr) * wprev_s[g * NQ + n];
        }
        __syncthreads();

        // ---- P7: read-head circular conv + sharpen ----
        #pragma unroll
        for (int g = 0; g < GQ; g++) {
            float s0 = p_s[22 * GQ + g], s1 = p_s[23 * GQ + g], s2 = p_s[24 * GQ + g];
            float gam = p_s[25 * GQ + g];
            const float* wb = &wbuf[g * NQ];
            float ws = s0 * wb[(n + 1) & 127] + s1 * wb[n] + s2 * wb[(n - 1) & 127];
            float wp = __expf(gam * __logf(ws));
            wr_s[g * NQ + n] = wp;
            float sp = warp_sum(wp);
            if (lane == 0) red[g * 4 + warp] = sp;   // slots 0..15 only (sumw survives in 16..31)
        }
        __syncthreads();

        // ---- P8: normalize w_r; write-head interpolation -> wbuf ----
        #pragma unroll
        for (int g = 0; g < GQ; g++) {
            float sp = red[g * 4 + 0] + red[g * 4 + 1] + red[g * 4 + 2] + red[g * 4 + 3];
            float wr = fdiv_(wr_s[g * NQ + n], sp + EPSQ);
            wr_s[g * NQ + n] = wr;
            float sumw = red[16 + g * 4 + 0] + red[16 + g * 4 + 1]
                       + red[16 + g * 4 + 2] + red[16 + g * 4 + 3];
            float gw = p_s[47 * GQ + g];
            wbuf[g * NQ + n] = gw * fdiv_(ew_s[g * NQ + n], sumw) + (1.f - gw) * wr;
        }
        __syncthreads();

        // ---- P9a: r = w_r @ M  (warp-per-batch) ----
        {
            int g = warp;
            const float* wrp = &wr_s[g * NQ];
            float w0 = wrp[lane], w1 = wrp[lane + 32], w2 = wrp[lane + 64], w3 = wrp[lane + 96];
            const float* Mg = &M_s[g * NQ * MPAD];
            #pragma unroll
            for (int v = 0; v < VQ; v++) {
                float acc = w0 * Mg[lane * MPAD + v] + w1 * Mg[(lane + 32) * MPAD + v]
                          + w2 * Mg[(lane + 64) * MPAD + v] + w3 * Mg[(lane + 96) * MPAD + v];
                acc = warp_sum(acc);
                if (lane == 0) z_s[(IQ + v) * GQ + g] = acc;
            }
        }
        // ---- P9b: write-head conv + sharpen ----
        #pragma unroll
        for (int g = 0; g < GQ; g++) {
            float s0 = p_s[48 * GQ + g], s1 = p_s[49 * GQ + g], s2 = p_s[50 * GQ + g];
            float gam = p_s[51 * GQ + g];
            const float* wb = &wbuf[g * NQ];
            float ws = s0 * wb[(n + 1) & 127] + s1 * wb[n] + s2 * wb[(n - 1) & 127];
            float wp = __expf(gam * __logf(ws));
            ew_s[g * NQ + n] = wp;
            float sp = warp_sum(wp);
            if (lane == 0) red[g * 4 + warp] = sp;
        }
        __syncthreads();

        // ---- P10: normalize w_w; M update; output; prefetch x ----
        #pragma unroll
        for (int g = 0; g < GQ; g++) {
            float sp = red[g * 4 + 0] + red[g * 4 + 1] + red[g * 4 + 2] + red[g * 4 + 3];
            float ww = fdiv_(ew_s[g * NQ + n], sp + EPSQ);
            wprev_s[g * NQ + n] = ww;
            float* Mrow = &M_s[(g * NQ + n) * MPAD];
            #pragma unroll
            for (int v = 0; v < VQ; v++) {
                float e = p_s[(52 + v) * GQ + g];
                float a = p_s[(72 + v) * GQ + g];
                float m = Mrow[v];
                m = fmaf(-ww * e, m, m);
                m = fmaf(ww, a, m);
                Mrow[v] = m;
            }
        }
        // out = sigmoid([h, r] @ Wf + bf)   (warp-per-batch, 8 outs x 4 partials)
        {
            int g = warp;
            int o = lane & 7, part = lane >> 3;
            float acc = 0.f;
            int j0 = part * 30;
            #pragma unroll 5
            for (int j = j0; j < j0 + 30; j++) {
                float c = (j < CQ) ? h_s[j * GQ + g] : z_s[(IQ + (j - CQ)) * GQ + g];
                acc = fmaf(c, Wf[j * OQ + o], acc);
            }
            acc += __shfl_xor_sync(0xffffffffu, acc, 8);
            acc += __shfl_xor_sync(0xffffffffu, acc, 16);
            if (lane < 8)
                out[((b0 + g) * TQ + t) * OQ + o] = fsigmoid_(acc + bfv);
        }
        // prefetch next x_t
        if (t + 1 < TQ && tid < IQ * GQ) {
            int g = tid / IQ, i = tid - g * IQ;
            z_s[i * GQ + g] = x[((b0 + g) * TQ + (t + 1)) * IQ + i];
        }
        __syncthreads();
    }
}

extern "C" void kernel_launch(void* const* d_in, const int* in_sizes, int n_in,
                              void* d_out, int out_size) {
    const float* x      = (const float*)d_in[0];
    const float* Wc     = (const float*)d_in[1];
    const float* bc     = (const float*)d_in[2];
    const float* Wr     = (const float*)d_in[3];
    const float* br     = (const float*)d_in[4];
    const float* Ww     = (const float*)d_in[5];
    const float* bw     = (const float*)d_in[6];
    const float* Wf     = (const float*)d_in[7];
    const float* bf     = (const float*)d_in[8];
    const float* r_bias = (const float*)d_in[9];
    const float* M_bias = (const float*)d_in[10];

    int B = in_sizes[0] / (TQ * IQ);        // 2048
    int grid = B / GQ;                      // 512

    size_t smem = (size_t)(GQ * NQ * MPAD + 4 * GQ * NQ + 32 * GQ + CQ * GQ
                           + 92 * GQ + 32) * sizeof(float);   // 54944 B
    cudaFuncSetAttribute(ntm_kernel, cudaFuncAttributeMaxDynamicSharedMemorySize, (int)smem);

    ntm_kernel<<<grid, BLK, smem>>>(x, Wc, bc, Wr, br, Ww, bw, Wf, bf,
                                    r_bias, M_bias, (float*)d_out);
}

// round 4
// speedup vs baseline: 1.6607x; 1.2961x over previous
#include <cuda_runtime.h>
#include <math.h>

#define TQ 64
#define IQ 9
#define NQ 128
#define VQ 20
#define CQ 100
#define OQ 8
#define GQ 4
#define BLK 128
#define EPSQ 1e-8f
#define PBLK 96

// p_s per-g block (96 floats, base g*96), all vector-aligned:
//  0..19 kr | 20..22 sr, 23 gammar | 24 betar, 25 gr, 26 betaw, 27 gw
//  28..30 sw, 31 gammaw | 32..51 kw | 52..71 e | 72..91 a | 92..95 pad

__device__ __forceinline__ float ftanh_(float x) {
    float xc = fminf(fmaxf(x, -15.f), 15.f);
    float e = __expf(2.f * xc);
    return __fdividef(e - 1.f, e + 1.f);
}
__device__ __forceinline__ float fsoftplus_(float x) {
    return fmaxf(x, 0.f) + __logf(1.f + __expf(-fabsf(x)));
}
__device__ __forceinline__ float fsigmoid_(float x) {
    return __fdividef(1.f, 1.f + __expf(-x));
}
__device__ __forceinline__ float apply_act(int at, float v) {
    switch (at) {
        case 0:  return ftanh_(v);
        case 1:  return fsoftplus_(v);
        case 2:  return fsigmoid_(v);
        case 3:  return __expf(v);
        default: return 1.f + fsoftplus_(v);
    }
}
__device__ __forceinline__ float warp_sum(float v) {
    v += __shfl_xor_sync(0xffffffffu, v, 16);
    v += __shfl_xor_sync(0xffffffffu, v, 8);
    v += __shfl_xor_sync(0xffffffffu, v, 4);
    v += __shfl_xor_sync(0xffffffffu, v, 2);
    v += __shfl_xor_sync(0xffffffffu, v, 1);
    return v;
}

__global__ __launch_bounds__(BLK, 4) void ntm_kernel(
    const float* __restrict__ x,
    const float* __restrict__ Wc, const float* __restrict__ bc,
    const float* __restrict__ Wr, const float* __restrict__ br,
    const float* __restrict__ Ww, const float* __restrict__ bw,
    const float* __restrict__ Wf, const float* __restrict__ bf,
    const float* __restrict__ r_bias, const float* __restrict__ M_bias,
    float* __restrict__ out)
{
    extern __shared__ float sm[];
    float* M_s     = sm;                    // [G][128][20]  10240 (80B rows, 16B aligned)
    float* wr_s    = M_s + GQ * NQ * VQ;    // [G][128]  er (unnormalized)
    float* ew_s    = wr_s + GQ * NQ;        // [G][128]  ew (unnormalized)
    float* wpr_s   = ew_s + GQ * NQ;        // [G][128]  wpr (read-head, pre-sharpen-norm)
    float* wprev_s = wpr_s + GQ * NQ;       // [G][128]  wprev -> wpw -> ww
    float* z_s     = wprev_s + GQ * NQ;     // [32][G]   controller input (x|r)
    float* h_s     = z_s + 32 * GQ;         // [100][G]  controller hidden
    float* p_s     = h_s + CQ * GQ;         // [G][96]   head params
    float* red     = p_s + GQ * PBLK;       // [3][16]   block-reduce partials

    const int tid  = threadIdx.x;
    const int lane = tid & 31;
    const int warp = tid >> 5;
    const int n    = tid;
    const int nm1  = (n - 1) & 127, np1 = (n + 1) & 127;
    const int b0   = blockIdx.x * GQ;

    // ---- hoisted per-thread constants ----
    float bcv = (tid < CQ) ? bc[tid] : 0.f;
    const float* Wp = Ww; int od = 66, cc = 0, st = 0, at = 0; float bsv = 0.f;
    {
        bool rh = (tid < 26);
        int c = rh ? tid : tid - 26;
        if (rh)           { Wp = Wr; od = 26; cc = c; bsv = br[c]; }
        else if (tid < 92) { cc = c; bsv = bw[c]; }
        if      (c < 20)  { st = (rh ? 0 : 32) + c;       at = 0; }
        else if (c == 20) { st = rh ? 24 : 26;            at = 1; }
        else if (c == 21) { st = rh ? 25 : 27;            at = 2; }
        else if (c < 25)  { st = (rh ? 20 : 28) + (c-22); at = 3; }
        else if (c == 25) { st = rh ? 23 : 31;            at = 4; }
        else if (c < 46)  { st = 52 + (c - 26);           at = 2; }
        else              { st = 72 + (c - 46);           at = 0; }
    }
    float bfv = bf[lane & 7];

    // ---- init state ----
    {
        float4 mb[5];
        const float4* Mb = (const float4*)M_bias;   // [128][5]
        #pragma unroll
        for (int i = 0; i < 5; i++) mb[i] = Mb[n * 5 + i];
        #pragma unroll
        for (int g = 0; g < GQ; g++) {
            wprev_s[g * NQ + n] = 0.f;
            float4* Mr = (float4*)&M_s[(g * NQ + n) * VQ];
            #pragma unroll
            for (int i = 0; i < 5; i++) Mr[i] = mb[i];
        }
    }
    if (tid < VQ * GQ) {                    // r0
        int g = tid & 3, v = tid >> 2;
        z_s[(IQ + v) * GQ + g] = r_bias[v];
    }
    if (tid < IQ * GQ) {                    // x_0
        int g = tid / IQ, i = tid - g * IQ;
        z_s[i * GQ + g] = x[(b0 + g) * TQ * IQ + i];
    }
    __syncthreads();

    for (int t = 0; t < TQ; t++) {
        // ---- P1: controller h = tanh([x,r] @ Wc + bc) ----
        if (tid < CQ) {
            float a0 = bcv, a1 = bcv, a2 = bcv, a3 = bcv;
            #pragma unroll
            for (int j = 0; j < IQ + VQ; j++) {
                float w = Wc[j * CQ + tid];
                float4 zv = *(const float4*)&z_s[j * GQ];
                a0 = fmaf(w, zv.x, a0); a1 = fmaf(w, zv.y, a1);
                a2 = fmaf(w, zv.z, a2); a3 = fmaf(w, zv.w, a3);
            }
            float4 hv = make_float4(ftanh_(a0), ftanh_(a1), ftanh_(a2), ftanh_(a3));
            *(float4*)&h_s[tid * GQ] = hv;
        }
        __syncthreads();

        // ---- P2: head matvecs + fused activations ----
        if (tid < 92) {
            float a0 = bsv, a1 = bsv, a2 = bsv, a3 = bsv;
            #pragma unroll 10
            for (int j = 0; j < CQ; j++) {
                float w = Wp[j * od + cc];
                float4 hv = *(const float4*)&h_s[j * GQ];
                a0 = fmaf(w, hv.x, a0); a1 = fmaf(w, hv.y, a1);
                a2 = fmaf(w, hv.z, a2); a3 = fmaf(w, hv.w, a3);
            }
            p_s[0 * PBLK + st] = apply_act(at, a0);
            p_s[1 * PBLK + st] = apply_act(at, a1);
            p_s[2 * PBLK + st] = apply_act(at, a2);
            p_s[3 * PBLK + st] = apply_act(at, a3);
        }
        __syncthreads();

        // ---- P5: fused content addressing, both heads ----
        #pragma unroll
        for (int g = 0; g < GQ; g++) {
            const float* pg = p_s + g * PBLK;
            float4 bv = *(const float4*)(pg + 24);      // betar, gr, betaw, gw
            const float4* Mrow = (const float4*)&M_s[(g * NQ + n) * VQ];
            const float4* krp  = (const float4*)pg;
            const float4* kwp  = (const float4*)(pg + 32);
            float dr = 0.f, dw = 0.f, n2 = 0.f, kr2 = 0.f, kw2 = 0.f;
            #pragma unroll
            for (int i = 0; i < 5; i++) {
                float4 m = Mrow[i], kr = krp[i], kw = kwp[i];
                dr = fmaf(kr.x, m.x, dr); dr = fmaf(kr.y, m.y, dr);
                dr = fmaf(kr.z, m.z, dr); dr = fmaf(kr.w, m.w, dr);
                dw = fmaf(kw.x, m.x, dw); dw = fmaf(kw.y, m.y, dw);
                dw = fmaf(kw.z, m.z, dw); dw = fmaf(kw.w, m.w, dw);
                n2 = fmaf(m.x, m.x, n2);  n2 = fmaf(m.y, m.y, n2);
                n2 = fmaf(m.z, m.z, n2);  n2 = fmaf(m.w, m.w, n2);
                kr2 = fmaf(kr.x, kr.x, kr2); kr2 = fmaf(kr.y, kr.y, kr2);
                kr2 = fmaf(kr.z, kr.z, kr2); kr2 = fmaf(kr.w, kr.w, kr2);
                kw2 = fmaf(kw.x, kw.x, kw2); kw2 = fmaf(kw.y, kw.y, kw2);
                kw2 = fmaf(kw.z, kw.z, kw2); kw2 = fmaf(kw.w, kw.w, kw2);
            }
            float mn = sqrtf(n2);
            float er  = __expf(bv.x * __fdividef(dr, sqrtf(kr2) * mn + EPSQ));
            float ewv = __expf(bv.z * __fdividef(dw, sqrtf(kw2) * mn + EPSQ));
            wr_s[g * NQ + n] = er;
            ew_s[g * NQ + n] = ewv;
            float sr = warp_sum(er), sw = warp_sum(ewv);
            if (lane == 0) { red[g * 4 + warp] = sr; red[16 + g * 4 + warp] = sw; }
        }
        // shift-softmax normalize (exp values -> probabilities), 2 heads x 4 g
        if (tid < 8) {
            int hh = tid >> 2, g = tid & 3;
            float* pg = p_s + g * PBLK;
            int sb = hh ? 28 : 20;
            float e0 = pg[sb], e1 = pg[sb + 1], e2 = pg[sb + 2];
            float inv = __fdividef(1.f, e0 + e1 + e2);
            pg[sb] = e0 * inv; pg[sb + 1] = e1 * inv; pg[sb + 2] = e2 * inv;
        }
        __syncthreads();

        // ---- P7: read-head conv + sharpen (interpolation inline) ----
        #pragma unroll
        for (int g = 0; g < GQ; g++) {
            const float* pg = p_s + g * PBLK;
            float4 sv = *(const float4*)(pg + 20);      // sr0,sr1,sr2,gammar
            float gr = pg[25];
            float se = red[g*4] + red[g*4+1] + red[g*4+2] + red[g*4+3];
            float ginv = gr * __fdividef(1.f, se);
            float omg  = 1.f - gr;
            const float* erp = &wr_s[g * NQ];
            const float* wpv = &wprev_s[g * NQ];
            float w_m = ginv * erp[nm1] + omg * wpv[nm1];
            float w_0 = ginv * erp[n]   + omg * wpv[n];
            float w_p = ginv * erp[np1] + omg * wpv[np1];
            float ws  = sv.x * w_p + sv.y * w_0 + sv.z * w_m;
            float wpr = __expf(sv.w * __logf(ws));
            wpr_s[g * NQ + n] = wpr;
            float sp = warp_sum(wpr);
            if (lane == 0) red[32 + g * 4 + warp] = sp;
        }
        __syncthreads();

        // ---- P9: write-head conv + sharpen (inline interp) AND r-readout ----
        #pragma unroll
        for (int g = 0; g < GQ; g++) {
            const float* pg = p_s + g * PBLK;
            float4 sv = *(const float4*)(pg + 28);      // sw0,sw1,sw2,gammaw
            float gw = pg[27];
            float sumw  = red[16 + g*4] + red[16 + g*4+1] + red[16 + g*4+2] + red[16 + g*4+3];
            float sp    = red[32 + g*4] + red[32 + g*4+1] + red[32 + g*4+2] + red[32 + g*4+3];
            float invsp = __fdividef(1.f, sp + EPSQ);
            float gwinv = gw * __fdividef(1.f, sumw);
            float omg   = 1.f - gw;
            float omgsp = omg * invsp;
            const float* wprp = &wpr_s[g * NQ];
            const float* ewp  = &ew_s[g * NQ];
            float w_m = gwinv * ewp[nm1] + omgsp * wprp[nm1];
            float w_0 = gwinv * ewp[n]   + omgsp * wprp[n];
            float w_p = gwinv * ewp[np1] + omgsp * wprp[np1];
            float ws  = sv.x * w_p + sv.y * w_0 + sv.z * w_m;
            float wpw = __expf(sv.w * __logf(ws));
            wprev_s[g * NQ + n] = wpw;                  // staged; normalized in P10
            float s2 = warp_sum(wpw);
            if (lane == 0) red[g * 4 + warp] = s2;      // er sums dead -> reuse slot 0
        }
        // r = w_r @ M (warp-per-g), normalization factored out
        {
            int g = warp;
            float sp = red[32 + g*4] + red[32 + g*4+1] + red[32 + g*4+2] + red[32 + g*4+3];
            float invsp = __fdividef(1.f, sp + EPSQ);
            const float* wprp = &wpr_s[g * NQ];
            float w0 = wprp[lane], w1 = wprp[lane + 32], w2 = wprp[lane + 64], w3 = wprp[lane + 96];
            const float4* M0 = (const float4*)&M_s[(g * NQ + lane) * VQ];
            const float4* M1 = (const float4*)&M_s[(g * NQ + lane + 32) * VQ];
            const float4* M2 = (const float4*)&M_s[(g * NQ + lane + 64) * VQ];
            const float4* M3 = (const float4*)&M_s[(g * NQ + lane + 96) * VQ];
            #pragma unroll
            for (int vb = 0; vb < 5; vb++) {
                float4 m0 = M0[vb], m1 = M1[vb], m2 = M2[vb], m3 = M3[vb];
                float ax = w0*m0.x + w1*m1.x + w2*m2.x + w3*m3.x;
                float ay = w0*m0.y + w1*m1.y + w2*m2.y + w3*m3.y;
                float az = w0*m0.z + w1*m1.z + w2*m2.z + w3*m3.z;
                float aw = w0*m0.w + w1*m1.w + w2*m2.w + w3*m3.w;
                ax = warp_sum(ax); ay = warp_sum(ay); az = warp_sum(az); aw = warp_sum(aw);
                if (lane == 0) {
                    int vbase = IQ + vb * 4;
                    z_s[(vbase + 0) * GQ + g] = ax * invsp;
                    z_s[(vbase + 1) * GQ + g] = ay * invsp;
                    z_s[(vbase + 2) * GQ + g] = az * invsp;
                    z_s[(vbase + 3) * GQ + g] = aw * invsp;
                }
            }
        }
        __syncthreads();

        // ---- P10: normalize w_w, M update, output, x prefetch ----
        #pragma unroll
        for (int g = 0; g < GQ; g++) {
            const float* pg = p_s + g * PBLK;
            float spw = red[g*4] + red[g*4+1] + red[g*4+2] + red[g*4+3];
            float ww = wprev_s[g * NQ + n] * __fdividef(1.f, spw + EPSQ);
            wprev_s[g * NQ + n] = ww;
            float4* Mrow = (float4*)&M_s[(g * NQ + n) * VQ];
            const float4* ep = (const float4*)(pg + 52);
            const float4* ap = (const float4*)(pg + 72);
            #pragma unroll
            for (int i = 0; i < 5; i++) {
                float4 m = Mrow[i], e = ep[i], a = ap[i];
                m.x = fmaf(ww, a.x, fmaf(-ww * e.x, m.x, m.x));
                m.y = fmaf(ww, a.y, fmaf(-ww * e.y, m.y, m.y));
                m.z = fmaf(ww, a.z, fmaf(-ww * e.z, m.z, m.z));
                m.w = fmaf(ww, a.w, fmaf(-ww * e.w, m.w, m.w));
                Mrow[i] = m;
            }
        }
        // out = sigmoid([h, r] @ Wf + bf)  (warp-per-g, 8 outs x 4 partials)
        {
            int g = warp;
            int o = lane & 7, part = lane >> 3;
            float acc = 0.f;
            int j0 = part * 30;
            #pragma unroll 5
            for (int j = j0; j < j0 + 30; j++) {
                float c = (j < CQ) ? h_s[j * GQ + g] : z_s[(IQ + (j - CQ)) * GQ + g];
                acc = fmaf(c, Wf[j * OQ + o], acc);
            }
            acc += __shfl_xor_sync(0xffffffffu, acc, 8);
            acc += __shfl_xor_sync(0xffffffffu, acc, 16);
            if (lane < 8)
                out[((b0 + g) * TQ + t) * OQ + o] = fsigmoid_(acc + bfv);
        }
        // prefetch next x_t
        if (t + 1 < TQ && tid < IQ * GQ) {
            int g = tid / IQ, i = tid - g * IQ;
            z_s[i * GQ + g] = x[((b0 + g) * TQ + (t + 1)) * IQ + i];
        }
        __syncthreads();
    }
}

extern "C" void kernel_launch(void* const* d_in, const int* in_sizes, int n_in,
                              void* d_out, int out_size) {
    const float* x      = (const float*)d_in[0];
    const float* Wc     = (const float*)d_in[1];
    const float* bc     = (const float*)d_in[2];
    const float* Wr     = (const float*)d_in[3];
    const float* br     = (const float*)d_in[4];
    const float* Ww     = (const float*)d_in[5];
    const float* bw     = (const float*)d_in[6];
    const float* Wf     = (const float*)d_in[7];
    const float* bf     = (const float*)d_in[8];
    const float* r_bias = (const float*)d_in[9];
    const float* M_bias = (const float*)d_in[10];

    int B = in_sizes[0] / (TQ * IQ);        // 2048
    int grid = B / GQ;                      // 512

    size_t smem = (size_t)(GQ * NQ * VQ + 4 * GQ * NQ + 32 * GQ + CQ * GQ
                           + GQ * PBLK + 48) * sizeof(float);   // 52992 B
    cudaFuncSetAttribute(ntm_kernel, cudaFuncAttributeMaxDynamicSharedMemorySize, (int)smem);

    ntm_kernel<<<grid, BLK, smem>>>(x, Wc, bc, Wr, br, Ww, bw, Wf, bf,
                                    r_bias, M_bias, (float*)d_out);
}